// round 16
// baseline (speedup 1.0000x reference)
#include <cuda_runtime.h>
#include <cuda_fp16.h>
#include <math.h>
#include <stdint.h>

#define H_ 56
#define W_ 56
#define HW_ 3136
#define N_ 16
#define C_ 256
#define CH_ 96
#define EPSBN 1e-3f

// Scratch: stacked GEMM output y[n][o][hw], o in [0,96):
//   rows 0..15 = x1, 16..31 = x2, 32..95 = x3
__device__ float g_y[N_ * CH_ * HW_];

// ---------------- helpers ----------------
__device__ __forceinline__ uint32_t smem_addr_u32(const void* p) {
    uint32_t a;
    asm("{ .reg .u64 t; cvta.to.shared.u64 t, %1; cvt.u32.u64 %0, t; }"
        : "=r"(a) : "l"(p));
    return a;
}

__device__ __forceinline__ void ldsm_x4(uint32_t* r, uint32_t addr) {
    asm volatile("ldmatrix.sync.aligned.m8n8.x4.shared.b16 {%0,%1,%2,%3}, [%4];"
                 : "=r"(r[0]), "=r"(r[1]), "=r"(r[2]), "=r"(r[3]) : "r"(addr));
}

__device__ __forceinline__ void ldsm_x2t(uint32_t* r, uint32_t addr) {
    asm volatile("ldmatrix.sync.aligned.m8n8.x2.trans.shared.b16 {%0,%1}, [%2];"
                 : "=r"(r[0]), "=r"(r[1]) : "r"(addr));
}

__device__ __forceinline__ void mma_fp16(float* d, const uint32_t* a,
                                         const uint32_t* b) {
    asm volatile(
        "mma.sync.aligned.m16n8k16.row.col.f32.f16.f16.f32 "
        "{%0,%1,%2,%3}, {%4,%5,%6,%7}, {%8,%9}, {%0,%1,%2,%3};"
        : "+f"(d[0]), "+f"(d[1]), "+f"(d[2]), "+f"(d[3])
        : "r"(a[0]), "r"(a[1]), "r"(a[2]), "r"(a[3]), "r"(b[0]), "r"(b[1]));
}

// packed f32x2 FMA and pack/dup/unpack helpers
__device__ __forceinline__ void fma2(unsigned long long& acc,
                                     unsigned long long a,
                                     unsigned long long b) {
    asm("fma.rn.f32x2 %0, %1, %2, %0;" : "+l"(acc) : "l"(a), "l"(b));
}
__device__ __forceinline__ unsigned long long dup2(float w) {
    unsigned long long r;
    asm("mov.b64 %0, {%1, %1};" : "=l"(r) : "f"(w));
    return r;
}
__device__ __forceinline__ unsigned long long pack2(float lo, float hi) {
    unsigned long long r;
    asm("mov.b64 %0, {%1, %2};" : "=l"(r) : "f"(lo), "f"(hi));
    return r;
}
__device__ __forceinline__ void unpack2(unsigned long long v, float& lo, float& hi) {
    asm("mov.b64 {%0, %1}, %2;" : "=f"(lo), "=f"(hi) : "l"(v));
}

// SW128 swizzle for 128B rows (16B granular)
#define SWZ(o) ((o) ^ (((o) >> 3) & 0x70))
// X-tile swizzle: rows of 256B (128 px fp16); XOR 16B-chunk index by k&7
#define XSWZ(k, pxb) ((k) * 256 + ((pxb) ^ (((k) & 7) << 4)))

// smem: X double buffer (2 x 16384) + W all 4 chunks (4 x 12288)
#define XBUF(i)  ((i) * 16384)
#define WALL_OFF 32768
#define WCHK(c)  (WALL_OFF + (c) * 12288)
#define SMEM_MMA 81920

// -------------------------------------------------------------------------
// Kernel 1: single-term fp16 GEMM via mma.sync (unchanged, ~17.5us).
// -------------------------------------------------------------------------
__global__ __launch_bounds__(256, 2) void sam_gemm_mma(
    const float* __restrict__ x,
    const float* __restrict__ w1,
    const float* __restrict__ w2,
    const float* __restrict__ w3) {
    extern __shared__ __align__(1024) char smem[];
    const int tid  = threadIdx.x;
    const int wid  = tid >> 5;
    const int lane = tid & 31;
    const int n    = blockIdx.y;
    int p0 = blockIdx.x * 128;
    if (p0 > HW_ - 128) p0 = HW_ - 128;   // overlap tile: identical dup writes

    const uint32_t sb = smem_addr_u32(smem);
    const float* xn = x + (size_t)n * C_ * HW_ + p0;

    float d[6][2][4];
#pragma unroll
    for (int m = 0; m < 6; m++)
#pragma unroll
        for (int nt = 0; nt < 2; nt++)
#pragma unroll
            for (int r = 0; r < 4; r++) d[m][nt][r] = 0.0f;

    const int xk = tid >> 5, xp4 = (tid & 31) * 4;
    const float* wrow_[3];
    int wq_[3];
#pragma unroll
    for (int i = 0; i < 3; i++) {
        int j = tid + i * 256;
        int o = j >> 3;
        wq_[i] = j & 7;
        wrow_[i] = (o < 16) ? (w1 + o * C_)
                 : (o < 32) ? (w2 + (o - 16) * C_)
                            : (w3 + (o - 32) * C_);
    }

    float4 Xr[8];

#define LOADX(kb)                                                              \
    _Pragma("unroll")                                                          \
    for (int i = 0; i < 8; i++)                                                \
        Xr[i] = *(const float4*)(xn + (size_t)((kb) + xk + i * 8) * HW_ + xp4)

#define STAGEX(bi)                                                             \
    _Pragma("unroll")                                                          \
    for (int i = 0; i < 8; i++) {                                              \
        int k = xk + i * 8;                                                    \
        float4 v = Xr[i];                                                      \
        __half2 h0 = __floats2half2_rn(v.x, v.y);                              \
        __half2 h1 = __floats2half2_rn(v.z, v.w);                              \
        int off = XSWZ(k, xp4 * 2);                                            \
        uint2 hw_; hw_.x = *(uint32_t*)&h0; hw_.y = *(uint32_t*)&h1;           \
        *(uint2*)(smem + XBUF(bi) + off) = hw_;                                \
    }

    LOADX(0);
    STAGEX(0);
    LOADX(64);
#pragma unroll
    for (int c = 0; c < 4; c++) {
        const int kb = c * 64;
#pragma unroll
        for (int i = 0; i < 3; i++) {
            int j = tid + i * 256;
            int o = j >> 3, q = j & 7;
            float4 va = *(const float4*)(wrow_[i] + kb + wq_[i] * 8);
            float4 vb = *(const float4*)(wrow_[i] + kb + wq_[i] * 8 + 4);
            __half2 h0 = __floats2half2_rn(va.x, va.y);
            __half2 h1 = __floats2half2_rn(va.z, va.w);
            __half2 h2 = __floats2half2_rn(vb.x, vb.y);
            __half2 h3 = __floats2half2_rn(vb.z, vb.w);
            int off = SWZ(o * 128 + q * 16);
            uint4 hv; hv.x = *(uint32_t*)&h0; hv.y = *(uint32_t*)&h1;
                      hv.z = *(uint32_t*)&h2; hv.w = *(uint32_t*)&h3;
            *(uint4*)(smem + WCHK(c) + off) = hv;
        }
    }
    __syncthreads();

    for (int c = 0; c < 4; c++) {
        const int xb = XBUF(c & 1);
        const int wb = WCHK(c);

#pragma unroll
        for (int ks = 0; ks < 4; ks++) {
            uint32_t bx[2][2];
            const int bk = ks * 16 + (lane & 15);
#pragma unroll
            for (int nt = 0; nt < 2; nt++) {
                int pxb = wid * 32 + nt * 16;
                ldsm_x2t(bx[nt], sb + xb + XSWZ(bk, pxb));
            }
            const int ach  = (lane & 15);
            const int acol = ks * 32 + ((lane >> 4) << 4);
#pragma unroll
            for (int m = 0; m < 6; m++) {
                uint32_t wf[4];
                ldsm_x4(wf, sb + wb + SWZ((m * 16 + ach) * 128 + acol));
#pragma unroll
                for (int nt = 0; nt < 2; nt++)
                    mma_fp16(d[m][nt], wf, bx[nt]);
            }
        }

        if (c < 3) {
            STAGEX((c + 1) & 1);
            if (c < 2) LOADX((c + 2) * 64);
            __syncthreads();
        }
    }
#undef LOADX
#undef STAGEX

    const int gid = lane >> 2, tig = lane & 3;
    float* yn = g_y + (size_t)n * CH_ * HW_;
    const int pxb = p0 + wid * 16 + 2 * tig;
#pragma unroll
    for (int m = 0; m < 6; m++) {
#pragma unroll
        for (int nt = 0; nt < 2; nt++) {
            int px = pxb + nt * 8;
            int ch = m * 16 + gid;
            float2 v0; v0.x = d[m][nt][0]; v0.y = d[m][nt][1];
            float2 v1; v1.x = d[m][nt][2]; v1.y = d[m][nt][3];
            *(float2*)&yn[(size_t)ch * HW_ + px] = v0;
            *(float2*)&yn[(size_t)(ch + 8) * HW_ + px] = v1;
        }
    }
}

// -------------------------------------------------------------------------
// Kernel 2: fused attention with a HALO TILE in smem.
// All reflected neighbor indices of a 64-px block lie in
// [max(0,hw0-64), min(HW,hw0+128)) (<=192 px). Channels 16..95 (x2+x3) for
// that window are loaded ONCE per block (14 coalesced float4/thread); all
// phase-1/2/3 neighbor reads become conflict-free LDS.
// smem layout (dynamic, bytes):
//   0     sw1p u64[18][8]   (1152)
//   1152  sw2p u64[16][4]   (512)
//   1664  scp  f32[4]       (16)
//   1680  sbn  f32[4][64]   (1024)
//   2704  sx1  f32[16][65]  (4160)
//   6864  sc_s f32[64*74]   (18944)
//   25808 sxh  f32[80][192] (61440)   total 87248
// -------------------------------------------------------------------------
#define A_SW1P 0
#define A_SW2P 1152
#define A_SCP  1664
#define A_SBN  1680
#define A_SX1  2704
#define A_SCS  6864
#define A_SXH  25808
#define SMEM_ATTN 87248

__global__ __launch_bounds__(288, 2) void sam_attn_kernel(
    const float* __restrict__ convp,
    const float* __restrict__ w1c,
    const float* __restrict__ w2c,
    const float* __restrict__ g1, const float* __restrict__ b1,
    const float* __restrict__ m1, const float* __restrict__ v1,
    const float* __restrict__ g2, const float* __restrict__ b2,
    const float* __restrict__ m2, const float* __restrict__ v2,
    float* __restrict__ out) {
    extern __shared__ __align__(16) char sm[];
    unsigned long long (*sw1p)[8] = (unsigned long long(*)[8])(sm + A_SW1P);
    unsigned long long (*sw2p)[4] = (unsigned long long(*)[4])(sm + A_SW2P);
    float* scp = (float*)(sm + A_SCP);
    float (*sbn)[64] = (float(*)[64])(sm + A_SBN);
    float (*sx1)[65] = (float(*)[65])(sm + A_SX1);
    float* sc_s = (float*)(sm + A_SCS);
    float (*sxh)[192] = (float(*)[192])(sm + A_SXH);

    const int t = threadIdx.x;
    const int n   = blockIdx.y;
    const int hw0 = blockIdx.x * 64;          // 3136/64 = 49 exact
    const int pix = t & 31;
    const int jj  = t >> 5;                   // 0..8

    const float* yn = g_y + (size_t)n * CH_ * HW_;

    // ---- Phase 0a: halo tile (issued first; latency under staging) ----
    const int base = (hw0 >= 64) ? hw0 - 64 : 0;
    const int end  = (hw0 + 128 <= HW_) ? hw0 + 128 : HW_;
    const int nf4  = (end - base) >> 2;       // <= 48
    for (int i = t; i < 80 * 48; i += 288) {
        int row = i / 48, f4 = i - row * 48;
        if (f4 < nf4) {
            float4 v = *(const float4*)(yn + (size_t)(16 + row) * HW_ + base + f4 * 4);
            *(float4*)&sxh[row][f4 * 4] = v;
        }
    }

    // ---- Phase 0b: weights, BN affines, center x1 ----
    if (t < 144) {
        int o2 = t & 7, c = t >> 3;
        sw1p[c][o2] = pack2(w1c[(2 * o2) * 18 + c], w1c[(2 * o2 + 1) * 18 + c]);
    }
    if (t < 64) {
        int o = t >> 2, q2 = t & 3;
        sw2p[o][q2] = pack2(w2c[(2 * q2) * 16 + o], w2c[(2 * q2 + 1) * 16 + o]);
    }
    if (t < 4) scp[t] = convp[t];
    if (t < 64) {
        const int phw = hw0 + t;
        float s1 = g1[phw] * rsqrtf(v1[phw] + EPSBN);
        float s2 = g2[phw] * rsqrtf(v2[phw] + EPSBN);
        sbn[0][t] = s1;
        sbn[1][t] = b1[phw] - m1[phw] * s1;
        sbn[2][t] = s2;
        sbn[3][t] = b2[phw] - m2[phw] * s2;
    }
#pragma unroll
    for (int i = 0; i < 4; i++) {
        int idx = t + i * 288;
        if (idx < 1024) {
            int c = idx >> 6, p = idx & 63;
            sx1[c][p] = yn[(size_t)c * HW_ + hw0 + p];
        }
    }
    __syncthreads();

    // ---- Phase 1: logits for (pixA, jj) and (pixB, jj), all-smem ----
    {
        const int pA = pix, pB = pix + 32;
        const int hwA = hw0 + pA, hwB = hw0 + pB;
        const int hA = hwA / W_, wA = hwA % W_;
        const int hB = hwB / W_, wB = hwB % W_;
        const float s1A = sbn[0][pA], o1A = sbn[1][pA];
        const float s2A = sbn[2][pA], o2A = sbn[3][pA];
        const float s1B = sbn[0][pB], o1B = sbn[1][pB];
        const float s2B = sbn[2][pB], o2B = sbn[3][pB];

        const int di = jj / 3 - 1, dj = jj % 3 - 1;
        int nhA = hA + di; nhA = (nhA < 0) ? -nhA : ((nhA >= H_) ? 2 * H_ - 2 - nhA : nhA);
        int nwA = wA + dj; nwA = (nwA < 0) ? -nwA : ((nwA >= W_) ? 2 * W_ - 2 - nwA : nwA);
        int nhB = hB + di; nhB = (nhB < 0) ? -nhB : ((nhB >= H_) ? 2 * H_ - 2 - nhB : nhB);
        int nwB = wB + dj; nwB = (nwB < 0) ? -nwB : ((nwB >= W_) ? 2 * W_ - 2 - nwB : nwB);
        const int lA = nhA * W_ + nwA - base;   // halo-local
        const int lB = nhB * W_ + nwB - base;

        float aA[18], aB[18];
#pragma unroll
        for (int c = 0; c < 16; c++) {
            float rA = sx1[c][pA] - sxh[c][lA];
            float rB = sx1[c][pB] - sxh[c][lB];
            aA[c] = fmaxf(fmaf(rA, s1A, o1A), 0.0f);
            aB[c] = fmaxf(fmaf(rB, s1B, o1B), 0.0f);
        }
        {
            const float lwA = -1.0f + 2.0f * (float)wA / 55.0f;
            const float lhA = -1.0f + 2.0f * (float)hA / 55.0f;
            const float nlwA = -1.0f + 2.0f * (float)nwA / 55.0f;
            const float nlhA = -1.0f + 2.0f * (float)nhA / 55.0f;
            aA[16] = fmaxf(fmaf(scp[0] * (lwA - nlwA) + scp[1] * (lhA - nlhA), s1A, o1A), 0.0f);
            aA[17] = fmaxf(fmaf(scp[2] * (lwA - nlwA) + scp[3] * (lhA - nlhA), s1A, o1A), 0.0f);
            const float lwB = -1.0f + 2.0f * (float)wB / 55.0f;
            const float lhB = -1.0f + 2.0f * (float)hB / 55.0f;
            const float nlwB = -1.0f + 2.0f * (float)nwB / 55.0f;
            const float nlhB = -1.0f + 2.0f * (float)nhB / 55.0f;
            aB[16] = fmaxf(fmaf(scp[0] * (lwB - nlwB) + scp[1] * (lhB - nlhB), s1B, o1B), 0.0f);
            aB[17] = fmaxf(fmaf(scp[2] * (lwB - nlwB) + scp[3] * (lhB - nlhB), s1B, o1B), 0.0f);
        }

        // matvec1 packed: weights loaded once, used for A and B
        unsigned long long hA2[8], hB2[8];
#pragma unroll
        for (int o2 = 0; o2 < 8; o2++) { hA2[o2] = 0ull; hB2[o2] = 0ull; }
#pragma unroll
        for (int c = 0; c < 18; c++) {
            unsigned long long adA = dup2(aA[c]);
            unsigned long long adB = dup2(aB[c]);
            ulonglong2 p0 = *(const ulonglong2*)&sw1p[c][0];
            ulonglong2 p1 = *(const ulonglong2*)&sw1p[c][2];
            ulonglong2 p2 = *(const ulonglong2*)&sw1p[c][4];
            ulonglong2 p3 = *(const ulonglong2*)&sw1p[c][6];
            fma2(hA2[0], p0.x, adA); fma2(hB2[0], p0.x, adB);
            fma2(hA2[1], p0.y, adA); fma2(hB2[1], p0.y, adB);
            fma2(hA2[2], p1.x, adA); fma2(hB2[2], p1.x, adB);
            fma2(hA2[3], p1.y, adA); fma2(hB2[3], p1.y, adB);
            fma2(hA2[4], p2.x, adA); fma2(hB2[4], p2.x, adB);
            fma2(hA2[5], p2.y, adA); fma2(hB2[5], p2.y, adB);
            fma2(hA2[6], p3.x, adA); fma2(hB2[6], p3.x, adB);
            fma2(hA2[7], p3.y, adA); fma2(hB2[7], p3.y, adB);
        }
        float hbA[16], hbB[16];
#pragma unroll
        for (int o2 = 0; o2 < 8; o2++) {
            float lo, hi;
            unpack2(hA2[o2], lo, hi);
            hbA[2 * o2]     = fmaxf(fmaf(lo, s2A, o2A), 0.0f);
            hbA[2 * o2 + 1] = fmaxf(fmaf(hi, s2A, o2A), 0.0f);
            unpack2(hB2[o2], lo, hi);
            hbB[2 * o2]     = fmaxf(fmaf(lo, s2B, o2B), 0.0f);
            hbB[2 * o2 + 1] = fmaxf(fmaf(hi, s2B, o2B), 0.0f);
        }

        // matvec2 packed
        unsigned long long sA2[4], sB2[4];
#pragma unroll
        for (int q2 = 0; q2 < 4; q2++) { sA2[q2] = 0ull; sB2[q2] = 0ull; }
#pragma unroll
        for (int o = 0; o < 16; o++) {
            unsigned long long adA = dup2(hbA[o]);
            unsigned long long adB = dup2(hbB[o]);
            ulonglong2 q0 = *(const ulonglong2*)&sw2p[o][0];
            ulonglong2 q1 = *(const ulonglong2*)&sw2p[o][2];
            fma2(sA2[0], q0.x, adA); fma2(sB2[0], q0.x, adB);
            fma2(sA2[1], q0.y, adA); fma2(sB2[1], q0.y, adB);
            fma2(sA2[2], q1.x, adA); fma2(sB2[2], q1.x, adB);
            fma2(sA2[3], q1.y, adA); fma2(sB2[3], q1.y, adB);
        }
        float* dA = &sc_s[pA * 74 + jj * 8];
        *(unsigned long long*)&dA[0] = sA2[0];
        *(unsigned long long*)&dA[2] = sA2[1];
        *(unsigned long long*)&dA[4] = sA2[2];
        *(unsigned long long*)&dA[6] = sA2[3];
        float* dB = &sc_s[pB * 74 + jj * 8];
        *(unsigned long long*)&dB[0] = sB2[0];
        *(unsigned long long*)&dB[2] = sB2[1];
        *(unsigned long long*)&dB[4] = sB2[2];
        *(unsigned long long*)&dB[6] = sB2[3];
    }
    __syncthreads();

    // ---- Phase 2+3 fused, two pixels per thread, thread=(q,pix) ----
    if (t < 256) {
        const int q = t >> 5;
        float* onb = out + (size_t)n * 64 * HW_;

#pragma unroll
        for (int half = 0; half < 2; half++) {
            const int p = pix + half * 32;
            const int hw = hw0 + p;
            const int h = hw / W_, w = hw % W_;

            const float* sbase = &sc_s[p * 74 + q];
            float v[9];
#pragma unroll
            for (int j = 0; j < 9; j++) v[j] = sbase[j * 8];
            float mx = v[0];
#pragma unroll
            for (int j = 1; j < 9; j++) mx = fmaxf(mx, v[j]);
            float sum = 0.0f;
#pragma unroll
            for (int j = 0; j < 9; j++) { v[j] = __expf(v[j] - mx); sum += v[j]; }
            float inv = 1.0f / sum;
#pragma unroll
            for (int j = 0; j < 9; j++) v[j] *= inv;

            float acc[8];
#pragma unroll
            for (int g = 0; g < 8; g++) acc[g] = 0.0f;
#pragma unroll
            for (int j = 0; j < 9; j++) {
                int nh = h + j / 3 - 1;
                nh = (nh < 0) ? -nh : ((nh >= H_) ? 2 * H_ - 2 - nh : nh);
                int nw = w + j % 3 - 1;
                nw = (nw < 0) ? -nw : ((nw >= W_) ? 2 * W_ - 2 - nw : nw);
                const int l = nh * W_ + nw - base;
                const float wj = v[j];
#pragma unroll
                for (int g = 0; g < 8; g++)
                    acc[g] = fmaf(wj, sxh[16 + g * 8 + q][l], acc[g]);
            }
            float* on = onb + hw;
#pragma unroll
            for (int g = 0; g < 8; g++)
                on[(size_t)(g * 8 + q) * HW_] = acc[g];
        }
    }
}

// -------------------------------------------------------------------------
// Launcher.
// -------------------------------------------------------------------------
extern "C" void kernel_launch(void* const* d_in, const int* in_sizes, int n_in,
                              void* d_out, int out_size) {
    const float* x   = (const float*)d_in[0];
    const float* w1  = (const float*)d_in[1];
    const float* w2  = (const float*)d_in[2];
    const float* w3  = (const float*)d_in[3];
    const float* cp  = (const float*)d_in[4];
    const float* cw1 = (const float*)d_in[5];
    const float* cw2 = (const float*)d_in[6];
    const float* g1  = (const float*)d_in[7];
    const float* b1  = (const float*)d_in[8];
    const float* m1  = (const float*)d_in[9];
    const float* v1  = (const float*)d_in[10];
    const float* g2  = (const float*)d_in[11];
    const float* b2  = (const float*)d_in[12];
    const float* m2  = (const float*)d_in[13];
    const float* v2  = (const float*)d_in[14];
    float* out = (float*)d_out;

    cudaFuncSetAttribute(sam_gemm_mma,
                         cudaFuncAttributeMaxDynamicSharedMemorySize, SMEM_MMA);
    cudaFuncSetAttribute(sam_attn_kernel,
                         cudaFuncAttributeMaxDynamicSharedMemorySize, SMEM_ATTN);

    dim3 gg(25, N_);                  // 25 px tiles (last clamped) x 16 n
    sam_gemm_mma<<<gg, 256, SMEM_MMA>>>(x, w1, w2, w3);

    dim3 ga(HW_ / 64, N_);            // 49 x 16
    sam_attn_kernel<<<ga, 288, SMEM_ATTN>>>(cp, cw1, cw2,
                                            g1, b1, m1, v1,
                                            g2, b2, m2, v2, out);
}

// round 17
// speedup vs baseline: 1.1684x; 1.1684x over previous
#include <cuda_runtime.h>
#include <cuda_fp16.h>
#include <math.h>
#include <stdint.h>

#define H_ 56
#define W_ 56
#define HW_ 3136
#define N_ 16
#define C_ 256
#define CH_ 96
#define EPSBN 1e-3f

// Scratch: stacked GEMM output y[n][o][hw], o in [0,96):
//   rows 0..15 = x1, 16..31 = x2, 32..95 = x3
__device__ float g_y[N_ * CH_ * HW_];

// ---------------- helpers ----------------
__device__ __forceinline__ uint32_t smem_addr_u32(const void* p) {
    uint32_t a;
    asm("{ .reg .u64 t; cvta.to.shared.u64 t, %1; cvt.u32.u64 %0, t; }"
        : "=r"(a) : "l"(p));
    return a;
}

__device__ __forceinline__ void ldsm_x4(uint32_t* r, uint32_t addr) {
    asm volatile("ldmatrix.sync.aligned.m8n8.x4.shared.b16 {%0,%1,%2,%3}, [%4];"
                 : "=r"(r[0]), "=r"(r[1]), "=r"(r[2]), "=r"(r[3]) : "r"(addr));
}

__device__ __forceinline__ void ldsm_x2t(uint32_t* r, uint32_t addr) {
    asm volatile("ldmatrix.sync.aligned.m8n8.x2.trans.shared.b16 {%0,%1}, [%2];"
                 : "=r"(r[0]), "=r"(r[1]) : "r"(addr));
}

__device__ __forceinline__ void mma_fp16(float* d, const uint32_t* a,
                                         const uint32_t* b) {
    asm volatile(
        "mma.sync.aligned.m16n8k16.row.col.f32.f16.f16.f32 "
        "{%0,%1,%2,%3}, {%4,%5,%6,%7}, {%8,%9}, {%0,%1,%2,%3};"
        : "+f"(d[0]), "+f"(d[1]), "+f"(d[2]), "+f"(d[3])
        : "r"(a[0]), "r"(a[1]), "r"(a[2]), "r"(a[3]), "r"(b[0]), "r"(b[1]));
}

// packed f32x2 FMA and pack/dup/unpack helpers
__device__ __forceinline__ void fma2(unsigned long long& acc,
                                     unsigned long long a,
                                     unsigned long long b) {
    asm("fma.rn.f32x2 %0, %1, %2, %0;" : "+l"(acc) : "l"(a), "l"(b));
}
__device__ __forceinline__ unsigned long long dup2(float w) {
    unsigned long long r;
    asm("mov.b64 %0, {%1, %1};" : "=l"(r) : "f"(w));
    return r;
}
__device__ __forceinline__ unsigned long long pack2(float lo, float hi) {
    unsigned long long r;
    asm("mov.b64 %0, {%1, %2};" : "=l"(r) : "f"(lo), "f"(hi));
    return r;
}
__device__ __forceinline__ void unpack2(unsigned long long v, float& lo, float& hi) {
    asm("mov.b64 {%0, %1}, %2;" : "=f"(lo), "=f"(hi) : "l"(v));
}

// SW128 swizzle for 128B rows (16B granular)
#define SWZ(o) ((o) ^ (((o) >> 3) & 0x70))
// X-tile swizzle: rows of 256B (128 px fp16); XOR 16B-chunk index by k&7
#define XSWZ(k, pxb) ((k) * 256 + ((pxb) ^ (((k) & 7) << 4)))

// smem: X double buffer (2 x 16384) + W all 4 chunks (4 x 12288)
#define XBUF(i)  ((i) * 16384)
#define WALL_OFF 32768
#define WCHK(c)  (WALL_OFF + (c) * 12288)
#define SMEM_MMA 81920

// -------------------------------------------------------------------------
// Kernel 1: single-term fp16 GEMM via mma.sync (R14 version, ~17.5us).
// D[ch=96, px=128] = Wf16[96,256] @ Xf16[256, px]
// ALL of W staged once in the prologue; loop stages only X (double-buffered,
// reg-prefetched). One barrier per chunk.
// -------------------------------------------------------------------------
__global__ __launch_bounds__(256, 2) void sam_gemm_mma(
    const float* __restrict__ x,
    const float* __restrict__ w1,
    const float* __restrict__ w2,
    const float* __restrict__ w3) {
    extern __shared__ __align__(1024) char smem[];
    const int tid  = threadIdx.x;
    const int wid  = tid >> 5;
    const int lane = tid & 31;
    const int n    = blockIdx.y;
    int p0 = blockIdx.x * 128;
    if (p0 > HW_ - 128) p0 = HW_ - 128;   // overlap tile: identical dup writes

    const uint32_t sb = smem_addr_u32(smem);
    const float* xn = x + (size_t)n * C_ * HW_ + p0;

    float d[6][2][4];
#pragma unroll
    for (int m = 0; m < 6; m++)
#pragma unroll
        for (int nt = 0; nt < 2; nt++)
#pragma unroll
            for (int r = 0; r < 4; r++) d[m][nt][r] = 0.0f;

    const int xk = tid >> 5, xp4 = (tid & 31) * 4;
    const float* wrow_[3];
    int wq_[3];
#pragma unroll
    for (int i = 0; i < 3; i++) {
        int j = tid + i * 256;
        int o = j >> 3;
        wq_[i] = j & 7;
        wrow_[i] = (o < 16) ? (w1 + o * C_)
                 : (o < 32) ? (w2 + (o - 16) * C_)
                            : (w3 + (o - 32) * C_);
    }

    float4 Xr[8];

#define LOADX(kb)                                                              \
    _Pragma("unroll")                                                          \
    for (int i = 0; i < 8; i++)                                                \
        Xr[i] = *(const float4*)(xn + (size_t)((kb) + xk + i * 8) * HW_ + xp4)

#define STAGEX(bi)                                                             \
    _Pragma("unroll")                                                          \
    for (int i = 0; i < 8; i++) {                                              \
        int k = xk + i * 8;                                                    \
        float4 v = Xr[i];                                                      \
        __half2 h0 = __floats2half2_rn(v.x, v.y);                              \
        __half2 h1 = __floats2half2_rn(v.z, v.w);                              \
        int off = XSWZ(k, xp4 * 2);                                            \
        uint2 hw_; hw_.x = *(uint32_t*)&h0; hw_.y = *(uint32_t*)&h1;           \
        *(uint2*)(smem + XBUF(bi) + off) = hw_;                                \
    }

    LOADX(0);
    STAGEX(0);
    LOADX(64);
#pragma unroll
    for (int c = 0; c < 4; c++) {
        const int kb = c * 64;
#pragma unroll
        for (int i = 0; i < 3; i++) {
            int j = tid + i * 256;
            int o = j >> 3, q = j & 7;
            float4 va = *(const float4*)(wrow_[i] + kb + wq_[i] * 8);
            float4 vb = *(const float4*)(wrow_[i] + kb + wq_[i] * 8 + 4);
            __half2 h0 = __floats2half2_rn(va.x, va.y);
            __half2 h1 = __floats2half2_rn(va.z, va.w);
            __half2 h2 = __floats2half2_rn(vb.x, vb.y);
            __half2 h3 = __floats2half2_rn(vb.z, vb.w);
            int off = SWZ(o * 128 + q * 16);
            uint4 hv; hv.x = *(uint32_t*)&h0; hv.y = *(uint32_t*)&h1;
                      hv.z = *(uint32_t*)&h2; hv.w = *(uint32_t*)&h3;
            *(uint4*)(smem + WCHK(c) + off) = hv;
        }
    }
    __syncthreads();

    for (int c = 0; c < 4; c++) {
        const int xb = XBUF(c & 1);
        const int wb = WCHK(c);

#pragma unroll
        for (int ks = 0; ks < 4; ks++) {
            uint32_t bx[2][2];
            const int bk = ks * 16 + (lane & 15);
#pragma unroll
            for (int nt = 0; nt < 2; nt++) {
                int pxb = wid * 32 + nt * 16;
                ldsm_x2t(bx[nt], sb + xb + XSWZ(bk, pxb));
            }
            const int ach  = (lane & 15);
            const int acol = ks * 32 + ((lane >> 4) << 4);
#pragma unroll
            for (int m = 0; m < 6; m++) {
                uint32_t wf[4];
                ldsm_x4(wf, sb + wb + SWZ((m * 16 + ach) * 128 + acol));
#pragma unroll
                for (int nt = 0; nt < 2; nt++)
                    mma_fp16(d[m][nt], wf, bx[nt]);
            }
        }

        if (c < 3) {
            STAGEX((c + 1) & 1);
            if (c < 2) LOADX((c + 2) * 64);
            __syncthreads();
        }
    }
#undef LOADX
#undef STAGEX

    const int gid = lane >> 2, tig = lane & 3;
    float* yn = g_y + (size_t)n * CH_ * HW_;
    const int pxb = p0 + wid * 16 + 2 * tig;
#pragma unroll
    for (int m = 0; m < 6; m++) {
#pragma unroll
        for (int nt = 0; nt < 2; nt++) {
            int px = pxb + nt * 8;
            int ch = m * 16 + gid;
            float2 v0; v0.x = d[m][nt][0]; v0.y = d[m][nt][1];
            float2 v1; v1.x = d[m][nt][2]; v1.y = d[m][nt][3];
            *(float2*)&yn[(size_t)ch * HW_ + px] = v0;
            *(float2*)&yn[(size_t)(ch + 8) * HW_ + px] = v1;
        }
    }
}

// -------------------------------------------------------------------------
// Kernel 2: fused attention (best-measured R11/R13 variant, 27.36us).
// 32 px/block, 1 px/thread; ch-major y gathers (L1-resident), packed f32x2
// matvecs, fused softmax+aggregation, no snhw/halo staging.
// -------------------------------------------------------------------------
__global__ __launch_bounds__(288, 4) void sam_attn_kernel(
    const float* __restrict__ convp,
    const float* __restrict__ w1c,
    const float* __restrict__ w2c,
    const float* __restrict__ g1, const float* __restrict__ b1,
    const float* __restrict__ m1, const float* __restrict__ v1,
    const float* __restrict__ g2, const float* __restrict__ b2,
    const float* __restrict__ m2, const float* __restrict__ v2,
    float* __restrict__ out) {
    __shared__ alignas(16) unsigned long long sw1p[18][8];  // [c][o-pair]
    __shared__ alignas(16) unsigned long long sw2p[16][4];  // [o][q-pair]
    __shared__ float scp[4];
    __shared__ float sbn[4][32];
    __shared__ float sx1[16][33];
    __shared__ float sc_s[32 * 74];   // [pix][q + 8*jj], stride 74 (8B-aligned)

    const int t = threadIdx.x;
    if (t < 144) {
        int o2 = t & 7, c = t >> 3;
        sw1p[c][o2] = pack2(w1c[(2 * o2) * 18 + c], w1c[(2 * o2 + 1) * 18 + c]);
    }
    if (t < 64) {
        int o = t >> 2, q2 = t & 3;
        sw2p[o][q2] = pack2(w2c[(2 * q2) * 16 + o], w2c[(2 * q2 + 1) * 16 + o]);
    }
    if (t < 4) scp[t] = convp[t];

    const int n   = blockIdx.y;
    const int hw0 = blockIdx.x * 32;
    const int pix = t & 31;
    const int jj  = t >> 5;
    const int hw  = hw0 + pix;
    const int h   = hw / W_;
    const int w   = hw % W_;

    const float* yn = g_y + (size_t)n * CH_ * HW_;

    // ---- Phase 0: BN affines + center x1 staging ----
    if (t < 32) {
        const int phw = hw0 + t;
        float s1 = g1[phw] * rsqrtf(v1[phw] + EPSBN);
        float s2 = g2[phw] * rsqrtf(v2[phw] + EPSBN);
        sbn[0][t] = s1;
        sbn[1][t] = b1[phw] - m1[phw] * s1;
        sbn[2][t] = s2;
        sbn[3][t] = b2[phw] - m2[phw] * s2;
    }
    if (t < 256) {
#pragma unroll
        for (int i = 0; i < 2; i++) {
            int idx = t + i * 256;
            int c = idx >> 5, p = idx & 31;
            sx1[c][p] = yn[(size_t)c * HW_ + hw0 + p];
        }
    }
    __syncthreads();

    // ---- Phase 1: logits for this (pix, jj) ----
    {
        const float s1 = sbn[0][pix], o1 = sbn[1][pix];
        const float s2 = sbn[2][pix], o2b = sbn[3][pix];

        int di = jj / 3 - 1, dj = jj % 3 - 1;
        int nh = h + di;
        nh = (nh < 0) ? -nh : ((nh >= H_) ? 2 * H_ - 2 - nh : nh);
        int nw = w + dj;
        nw = (nw < 0) ? -nw : ((nw >= W_) ? 2 * W_ - 2 - nw : nw);
        const int nhw = nh * W_ + nw;

        float a[18];
#pragma unroll
        for (int c = 0; c < 16; c++) {
            float r = sx1[c][pix] - yn[(size_t)(16 + c) * HW_ + nhw];
            a[c] = fmaxf(fmaf(r, s1, o1), 0.0f);
        }
        const float lw  = -1.0f + 2.0f * (float)w  / 55.0f;
        const float lh  = -1.0f + 2.0f * (float)h  / 55.0f;
        const float nlw = -1.0f + 2.0f * (float)nw / 55.0f;
        const float nlh = -1.0f + 2.0f * (float)nh / 55.0f;
        const float dp0 = scp[0] * (lw - nlw) + scp[1] * (lh - nlh);
        const float dp1 = scp[2] * (lw - nlw) + scp[3] * (lh - nlh);
        a[16] = fmaxf(fmaf(dp0, s1, o1), 0.0f);
        a[17] = fmaxf(fmaf(dp1, s1, o1), 0.0f);

        // matvec1 packed: hb2[o2] = (hb[2o2], hb[2o2+1])
        unsigned long long hb2[8];
#pragma unroll
        for (int o2 = 0; o2 < 8; o2++) hb2[o2] = 0ull;
#pragma unroll
        for (int c = 0; c < 18; c++) {
            unsigned long long ad = dup2(a[c]);
            ulonglong2 p0 = *(const ulonglong2*)&sw1p[c][0];
            ulonglong2 p1 = *(const ulonglong2*)&sw1p[c][2];
            ulonglong2 p2 = *(const ulonglong2*)&sw1p[c][4];
            ulonglong2 p3 = *(const ulonglong2*)&sw1p[c][6];
            fma2(hb2[0], p0.x, ad); fma2(hb2[1], p0.y, ad);
            fma2(hb2[2], p1.x, ad); fma2(hb2[3], p1.y, ad);
            fma2(hb2[4], p2.x, ad); fma2(hb2[5], p2.y, ad);
            fma2(hb2[6], p3.x, ad); fma2(hb2[7], p3.y, ad);
        }
        float hb[16];
#pragma unroll
        for (int o2 = 0; o2 < 8; o2++) {
            float lo, hi;
            unpack2(hb2[o2], lo, hi);
            hb[2 * o2]     = fmaxf(fmaf(lo, s2, o2b), 0.0f);
            hb[2 * o2 + 1] = fmaxf(fmaf(hi, s2, o2b), 0.0f);
        }

        // matvec2 packed
        unsigned long long sc2[4];
#pragma unroll
        for (int q2 = 0; q2 < 4; q2++) sc2[q2] = 0ull;
#pragma unroll
        for (int o = 0; o < 16; o++) {
            unsigned long long ad = dup2(hb[o]);
            ulonglong2 q0 = *(const ulonglong2*)&sw2p[o][0];
            ulonglong2 q1 = *(const ulonglong2*)&sw2p[o][2];
            fma2(sc2[0], q0.x, ad); fma2(sc2[1], q0.y, ad);
            fma2(sc2[2], q1.x, ad); fma2(sc2[3], q1.y, ad);
        }
        float* dst = &sc_s[pix * 74 + jj * 8];
        *(unsigned long long*)&dst[0] = sc2[0];
        *(unsigned long long*)&dst[2] = sc2[1];
        *(unsigned long long*)&dst[4] = sc2[2];
        *(unsigned long long*)&dst[6] = sc2[3];
    }
    __syncthreads();

    // ---- Phase 2+3 fused: softmax (regs) + aggregation, thread=(q,pix) ----
    if (t < 256) {
        const int q = t >> 5;
        const float* base = &sc_s[pix * 74 + q];
        float v[9];
#pragma unroll
        for (int j = 0; j < 9; j++) v[j] = base[j * 8];
        float mx = v[0];
#pragma unroll
        for (int j = 1; j < 9; j++) mx = fmaxf(mx, v[j]);
        float sum = 0.0f;
#pragma unroll
        for (int j = 0; j < 9; j++) { v[j] = __expf(v[j] - mx); sum += v[j]; }
        float inv = 1.0f / sum;
#pragma unroll
        for (int j = 0; j < 9; j++) v[j] *= inv;

        int nhw9[9];
#pragma unroll
        for (int j = 0; j < 9; j++) {
            int nh = h + j / 3 - 1;
            nh = (nh < 0) ? -nh : ((nh >= H_) ? 2 * H_ - 2 - nh : nh);
            int nw = w + j % 3 - 1;
            nw = (nw < 0) ? -nw : ((nw >= W_) ? 2 * W_ - 2 - nw : nw);
            nhw9[j] = nh * W_ + nw;
        }
        const float* y3 = yn + (size_t)(32 + q) * HW_;
        float acc[8];
#pragma unroll
        for (int g = 0; g < 8; g++) acc[g] = 0.0f;
#pragma unroll
        for (int j = 0; j < 9; j++) {
            const int nhw = nhw9[j];
            const float wj = v[j];
#pragma unroll
            for (int g = 0; g < 8; g++)
                acc[g] = fmaf(wj, y3[(size_t)(g * 8) * HW_ + nhw], acc[g]);
        }
        float* on = out + (size_t)n * 64 * HW_ + hw;
#pragma unroll
        for (int g = 0; g < 8; g++)
            on[(size_t)(g * 8 + q) * HW_] = acc[g];
    }
}

// -------------------------------------------------------------------------
// Launcher.
// -------------------------------------------------------------------------
extern "C" void kernel_launch(void* const* d_in, const int* in_sizes, int n_in,
                              void* d_out, int out_size) {
    const float* x   = (const float*)d_in[0];
    const float* w1  = (const float*)d_in[1];
    const float* w2  = (const float*)d_in[2];
    const float* w3  = (const float*)d_in[3];
    const float* cp  = (const float*)d_in[4];
    const float* cw1 = (const float*)d_in[5];
    const float* cw2 = (const float*)d_in[6];
    const float* g1  = (const float*)d_in[7];
    const float* b1  = (const float*)d_in[8];
    const float* m1  = (const float*)d_in[9];
    const float* v1  = (const float*)d_in[10];
    const float* g2  = (const float*)d_in[11];
    const float* b2  = (const float*)d_in[12];
    const float* m2  = (const float*)d_in[13];
    const float* v2  = (const float*)d_in[14];
    float* out = (float*)d_out;

    cudaFuncSetAttribute(sam_gemm_mma,
                         cudaFuncAttributeMaxDynamicSharedMemorySize, SMEM_MMA);

    dim3 gg(25, N_);                  // 25 px tiles (last clamped) x 16 n
    sam_gemm_mma<<<gg, 256, SMEM_MMA>>>(x, w1, w2, w3);

    dim3 ga(HW_ / 32, N_);            // 98 x 16
    sam_attn_kernel<<<ga, 288>>>(cp, cw1, cw2,
                                 g1, b1, m1, v1,
                                 g2, b2, m2, v2, out);
}